// round 3
// baseline (speedup 1.0000x reference)
#include <cuda_runtime.h>
#include <math.h>

#define B_    8
#define C_    256
#define T_    2048
#define SC_   64
#define DEPTH_ 256
#define OCH   384          // q(64) | k(64) | v(256)
#define SS_STR 321
#define NCOL  320

// scratch (no allocation allowed)
__device__ float g_Wf[OCH * C_];
__device__ float g_bf[OCH];
__device__ float g_qkv[B_ * T_ * OCH];   // [b][t][384] : q 0..63, k 64..127, v 128..383
__device__ float g_denom[T_];

// ---------------------------------------------------------------------------
// Fold BN into conv weights: W'[o][c] = W*g/sqrt(var+eps); b' = (b-mu)*inv+beta
// ---------------------------------------------------------------------------
__global__ void fold_k(
    const float* __restrict__ kW, const float* __restrict__ kb, const float* __restrict__ kg,
    const float* __restrict__ kbe, const float* __restrict__ kmu, const float* __restrict__ kva,
    const float* __restrict__ qW, const float* __restrict__ qb, const float* __restrict__ qg,
    const float* __restrict__ qbe, const float* __restrict__ qmu, const float* __restrict__ qva,
    const float* __restrict__ vW, const float* __restrict__ vb, const float* __restrict__ vg,
    const float* __restrict__ vbe, const float* __restrict__ vmu, const float* __restrict__ vva)
{
    int o = blockIdx.x, c = threadIdx.x;
    const float *W, *bb, *gg, *be, *mu, *va; int oo;
    if (o < 64)        { W=qW; bb=qb; gg=qg; be=qbe; mu=qmu; va=qva; oo=o;       }
    else if (o < 128)  { W=kW; bb=kb; gg=kg; be=kbe; mu=kmu; va=kva; oo=o-64;   }
    else               { W=vW; bb=vb; gg=vg; be=vbe; mu=vmu; va=vva; oo=o-128;  }
    float inv = gg[oo] * rsqrtf(va[oo] + 1e-5f);
    g_Wf[o * C_ + c] = W[oo * C_ + c] * inv;
    if (c == 0) g_bf[o] = (bb[oo] - mu[oo]) * inv + be[oo];
}

// ---------------------------------------------------------------------------
// Fused QKV projection: out[b][t][o] = relu( sum_c Wf[o][c]*x[b][c][t] + bf[o] )
// grid (T/64, OCH/64, B), 256 threads, 64x64 tile, K chunks of 32.
// ---------------------------------------------------------------------------
__global__ __launch_bounds__(256) void proj_k(const float* __restrict__ x)
{
    const int t0 = blockIdx.x * 64, o0 = blockIdx.y * 64, b = blockIdx.z;
    __shared__ float As[32 * 64];   // [kk][m]
    __shared__ float Bs[32 * 65];   // [kk][n] padded
    const int tid = threadIdx.x;
    const int mg = tid >> 4, ng = tid & 15;
    const int lm = tid & 63, lkb = tid >> 6;
    const int lk2 = tid & 31, lnb = tid >> 5;
    float acc[4][4] = {};

    for (int kc = 0; kc < C_; kc += 32) {
        #pragma unroll
        for (int i = 0; i < 8; i++) {
            int kk = lkb + i * 4;
            As[kk * 64 + lm] = x[(b * C_ + kc + kk) * T_ + t0 + lm];
        }
        #pragma unroll
        for (int i = 0; i < 8; i++) {
            int n = lnb + i * 8;
            Bs[lk2 * 65 + n] = g_Wf[(o0 + n) * C_ + kc + lk2];
        }
        __syncthreads();
        #pragma unroll
        for (int kk = 0; kk < 32; kk++) {
            float a[4], bv[4];
            #pragma unroll
            for (int i = 0; i < 4; i++) a[i] = As[kk * 64 + mg * 4 + i];
            #pragma unroll
            for (int j = 0; j < 4; j++) bv[j] = Bs[kk * 65 + ng * 4 + j];
            #pragma unroll
            for (int i = 0; i < 4; i++)
                #pragma unroll
                for (int j = 0; j < 4; j++) acc[i][j] += a[i] * bv[j];
        }
        __syncthreads();
    }
    #pragma unroll
    for (int i = 0; i < 4; i++) {
        float4 v;
        float t0v = acc[i][0] + g_bf[o0 + ng * 4 + 0];
        float t1v = acc[i][1] + g_bf[o0 + ng * 4 + 1];
        float t2v = acc[i][2] + g_bf[o0 + ng * 4 + 2];
        float t3v = acc[i][3] + g_bf[o0 + ng * 4 + 3];
        v.x = fmaxf(t0v, 0.f); v.y = fmaxf(t1v, 0.f);
        v.z = fmaxf(t2v, 0.f); v.w = fmaxf(t3v, 0.f);
        *(float4*)&g_qkv[(b * T_ + t0 + mg * 4 + i) * OCH + o0 + ng * 4] = v;
    }
}

// ---------------------------------------------------------------------------
// Banded attention. 64-row tile; band columns j=0..319 map s = t0-256+j.
// Valid j for row r: [max(r+1, 256-t0), r+256].
// DENOM=true: batch 0 only, writes g_denom[t] = sum(exp(s-m)) + 1e-30.
// DENOM=false: full attention, divides by g_denom (batch-0 sums, per ref).
// ---------------------------------------------------------------------------
template<bool DENOM>
__global__ __launch_bounds__(256) void attn_k(const float* __restrict__ x,
                                              float* __restrict__ y)
{
    extern __shared__ float sm[];
    float* Ss = sm;                        // 64*321 floats (also Outs in epilogue)
    float* Qs = sm + 64 * SS_STR;          // 64*65
    float* KV = Qs + 64 * 65;              // 64*256 (K tile uses stride 65 region)

    const int t0 = blockIdx.x * 64;
    const int b  = DENOM ? 0 : blockIdx.y;
    const int tid = threadIdx.x;
    const int sbase = t0 - DEPTH_;
    const int rg = tid >> 4, cg = tid & 15;

    // load Q tile [64 rows][64 d]
    {
        int d = tid & 63, rb = tid >> 6;
        #pragma unroll
        for (int i = 0; i < 16; i++) {
            int r = rb + i * 4;
            Qs[r * 65 + d] = g_qkv[(b * T_ + t0 + r) * OCH + d];
        }
    }

    // ---- scores: 5 chunks of 64 columns ----
    for (int kc = 0; kc < 5; kc++) {
        __syncthreads();
        {
            int d = tid & 63, rb = tid >> 6;
            #pragma unroll
            for (int i = 0; i < 16; i++) {
                int r = rb + i * 4;
                int s = sbase + kc * 64 + r;
                KV[r * 65 + d] = (s >= 0) ? g_qkv[(b * T_ + s) * OCH + 64 + d] : 0.f;
            }
        }
        __syncthreads();
        float cacc[4][4] = {};
        #pragma unroll 4
        for (int d = 0; d < 64; d++) {
            float qv[4], kv[4];
            #pragma unroll
            for (int i = 0; i < 4; i++) qv[i] = Qs[(rg * 4 + i) * 65 + d];
            #pragma unroll
            for (int j = 0; j < 4; j++) kv[j] = KV[(cg * 4 + j) * 65 + d];
            #pragma unroll
            for (int i = 0; i < 4; i++)
                #pragma unroll
                for (int j = 0; j < 4; j++) cacc[i][j] += qv[i] * kv[j];
        }
        #pragma unroll
        for (int i = 0; i < 4; i++)
            #pragma unroll
            for (int j = 0; j < 4; j++)
                Ss[(rg * 4 + i) * SS_STR + kc * 64 + cg * 4 + j] = cacc[i][j] * 0.125f;
    }
    __syncthreads();

    // ---- softmax (max includes 0 from masked entries, per reference) ----
    {
        int r = tid >> 2, g = tid & 3;
        int t = t0 + r;
        int jlo = max(r + 1, DEPTH_ - t0);
        int jhi = r + DEPTH_;
        float mx = 0.f;
        for (int j = jlo + g; j <= jhi; j += 4)
            mx = fmaxf(mx, Ss[r * SS_STR + j]);
        mx = fmaxf(mx, __shfl_xor_sync(0xffffffffu, mx, 1));
        mx = fmaxf(mx, __shfl_xor_sync(0xffffffffu, mx, 2));
        if (DENOM) {
            float sum = 0.f;
            for (int j = jlo + g; j <= jhi; j += 4)
                sum += expf(Ss[r * SS_STR + j] - mx);
            sum += __shfl_xor_sync(0xffffffffu, sum, 1);
            sum += __shfl_xor_sync(0xffffffffu, sum, 2);
            if (g == 0) g_denom[t] = sum + 1e-30f;
        } else {
            float invd = 1.f / g_denom[t];
            for (int j = g; j < NCOL; j += 4) {
                float v = Ss[r * SS_STR + j];
                Ss[r * SS_STR + j] = (j >= jlo && j <= jhi) ? expf(v - mx) * invd : 0.f;
            }
        }
    }
    if (DENOM) return;
    __syncthreads();

    // ---- P @ V : out tile [64 t][256 c], thread = 4t x 16c ----
    float4 acc[4][4];
    #pragma unroll
    for (int i = 0; i < 4; i++)
        #pragma unroll
        for (int q4 = 0; q4 < 4; q4++) acc[i][q4] = make_float4(0.f, 0.f, 0.f, 0.f);

    for (int kc = 0; kc < 5; kc++) {
        {
            int c4 = tid & 63, sb2 = tid >> 6;
            #pragma unroll
            for (int i = 0; i < 16; i++) {
                int srow = sb2 + i * 4;
                int s = sbase + kc * 64 + srow;
                float4 v = (s >= 0)
                    ? *(const float4*)&g_qkv[(b * T_ + s) * OCH + 128 + c4 * 4]
                    : make_float4(0.f, 0.f, 0.f, 0.f);
                *(float4*)&KV[srow * 256 + c4 * 4] = v;
            }
        }
        __syncthreads();
        #pragma unroll 2
        for (int jj = 0; jj < 64; jj++) {
            int j = kc * 64 + jj;
            float p[4];
            #pragma unroll
            for (int i = 0; i < 4; i++) p[i] = Ss[(rg * 4 + i) * SS_STR + j];
            float4 v[4];
            #pragma unroll
            for (int q4 = 0; q4 < 4; q4++)
                v[q4] = *(const float4*)&KV[jj * 256 + cg * 16 + q4 * 4];
            #pragma unroll
            for (int i = 0; i < 4; i++)
                #pragma unroll
                for (int q4 = 0; q4 < 4; q4++) {
                    acc[i][q4].x += p[i] * v[q4].x;
                    acc[i][q4].y += p[i] * v[q4].y;
                    acc[i][q4].z += p[i] * v[q4].z;
                    acc[i][q4].w += p[i] * v[q4].w;
                }
        }
        __syncthreads();
    }

    // ---- epilogue: transpose via swizzled smem, coalesced y = x + out ----
    float* Outs = Ss;   // reuse (16384 floats needed, 20544 available)
    #pragma unroll
    for (int i = 0; i < 4; i++)
        #pragma unroll
        for (int q4 = 0; q4 < 4; q4++) {
            int r  = rg * 4 + i;
            int cb = cg * 16 + q4 * 4;
            int xr = r ^ ((cb >> 2) & 63);   // same for cb..cb+3
            Outs[(cb + 0) * 64 + xr] = acc[i][q4].x;
            Outs[(cb + 1) * 64 + xr] = acc[i][q4].y;
            Outs[(cb + 2) * 64 + xr] = acc[i][q4].z;
            Outs[(cb + 3) * 64 + xr] = acc[i][q4].w;
        }
    __syncthreads();
    {
        int tt = tid & 63, cb2 = tid >> 6;
        #pragma unroll
        for (int k = 0; k < 64; k++) {
            int c = k * 4 + cb2;
            int gi = (b * C_ + c) * T_ + t0 + tt;
            y[gi] = x[gi] + Outs[c * 64 + (tt ^ ((c >> 2) & 63))];
        }
    }
}

// ---------------------------------------------------------------------------
extern "C" void kernel_launch(void* const* d_in, const int* in_sizes, int n_in,
                              void* d_out, int out_size)
{
    const float* x   = (const float*)d_in[0];
    const float* kW  = (const float*)d_in[1];
    const float* kb  = (const float*)d_in[2];
    const float* kg  = (const float*)d_in[3];
    const float* kbe = (const float*)d_in[4];
    const float* kmu = (const float*)d_in[5];
    const float* kva = (const float*)d_in[6];
    const float* qW  = (const float*)d_in[7];
    const float* qb  = (const float*)d_in[8];
    const float* qg  = (const float*)d_in[9];
    const float* qbe = (const float*)d_in[10];
    const float* qmu = (const float*)d_in[11];
    const float* qva = (const float*)d_in[12];
    const float* vW  = (const float*)d_in[13];
    const float* vb  = (const float*)d_in[14];
    const float* vg  = (const float*)d_in[15];
    const float* vbe = (const float*)d_in[16];
    const float* vmu = (const float*)d_in[17];
    const float* vva = (const float*)d_in[18];
    float* y = (float*)d_out;

    const int smem_attn = (64 * SS_STR + 64 * 65 + 64 * 256) * sizeof(float); // 164352
    cudaFuncSetAttribute(attn_k<true>,  cudaFuncAttributeMaxDynamicSharedMemorySize, smem_attn);
    cudaFuncSetAttribute(attn_k<false>, cudaFuncAttributeMaxDynamicSharedMemorySize, smem_attn);

    fold_k<<<OCH, C_>>>(kW, kb, kg, kbe, kmu, kva,
                        qW, qb, qg, qbe, qmu, qva,
                        vW, vb, vg, vbe, vmu, vva);
    proj_k<<<dim3(T_ / 64, OCH / 64, B_), 256>>>(x);
    attn_k<true><<<T_ / 64, 256, smem_attn>>>(x, y);                 // batch-0 denominators
    attn_k<false><<<dim3(T_ / 64, B_), 256, smem_attn>>>(x, y);      // full attention
}

// round 4
// speedup vs baseline: 1.5807x; 1.5807x over previous
#include <cuda_runtime.h>
#include <math.h>

#define B_     8
#define C_     256
#define T_     2048
#define SC_    64
#define DEPTH_ 256
#define OCH    384          // q(64) | k(64) | v(256)
#define NCOL   320
#define SSTR   324          // score row stride (floats), 324 mod 32 = 4 -> low conflicts
#define QSTR   68           // Qt row stride: 68*4=272 bytes, 16B aligned
#define KSTR   34

typedef unsigned long long u64t;

// scratch (no allocation allowed)
__device__ float g_Wt[C_ * OCH];         // transposed folded weights [c][o]
__device__ float g_bf[OCH];
__device__ float g_qkv[B_ * T_ * OCH];   // [b][t][384] : q 0..63, k 64..127, v 128..383
__device__ float g_denom[T_];

// ---- packed fp32 helpers (FFMA2 via PTX; ptxas never emits it itself) ----
__device__ __forceinline__ u64t pk2(float a, float b) {
    u64t r; asm("mov.b64 %0,{%1,%2};" : "=l"(r) : "f"(a), "f"(b)); return r;
}
__device__ __forceinline__ u64t dup2(float a) { return pk2(a, a); }
__device__ __forceinline__ void fma2(u64t& d, u64t a, u64t b) {
    asm("fma.rn.f32x2 %0,%1,%2,%3;" : "=l"(d) : "l"(a), "l"(b), "l"(d));
}
__device__ __forceinline__ void unpk(u64t v, float& x, float& y) {
    asm("mov.b64 {%0,%1},%2;" : "=f"(x), "=f"(y) : "l"(v));
}

// ---------------------------------------------------------------------------
// Fold BN into conv weights, store TRANSPOSED: g_Wt[c][o] = W[o][c]*inv
// grid(C_) x block(OCH) -> coalesced g_Wt writes.
// ---------------------------------------------------------------------------
__global__ void fold_k(
    const float* __restrict__ kW, const float* __restrict__ kb, const float* __restrict__ kg,
    const float* __restrict__ kbe, const float* __restrict__ kmu, const float* __restrict__ kva,
    const float* __restrict__ qW, const float* __restrict__ qb, const float* __restrict__ qg,
    const float* __restrict__ qbe, const float* __restrict__ qmu, const float* __restrict__ qva,
    const float* __restrict__ vW, const float* __restrict__ vb, const float* __restrict__ vg,
    const float* __restrict__ vbe, const float* __restrict__ vmu, const float* __restrict__ vva)
{
    int c = blockIdx.x, o = threadIdx.x;
    const float *W, *bb, *gg, *be, *mu, *va; int oo;
    if (o < 64)        { W=qW; bb=qb; gg=qg; be=qbe; mu=qmu; va=qva; oo=o;       }
    else if (o < 128)  { W=kW; bb=kb; gg=kg; be=kbe; mu=kmu; va=kva; oo=o-64;   }
    else               { W=vW; bb=vb; gg=vg; be=vbe; mu=vmu; va=vva; oo=o-128;  }
    float inv = gg[oo] * rsqrtf(va[oo] + 1e-5f);
    g_Wt[c * OCH + o] = W[oo * C_ + c] * inv;
    if (c == 0) g_bf[o] = (bb[oo] - mu[oo]) * inv + be[oo];
}

// ---------------------------------------------------------------------------
// QKV projection: 128x128 tile, 256 threads, 8x8 per thread, FFMA2 packed
// over the m (row) dimension. grid (T/128, OCH/128, B).
// ---------------------------------------------------------------------------
__global__ __launch_bounds__(256, 2) void proj_k(const float* __restrict__ x)
{
    const int t0 = blockIdx.x * 128, o0 = blockIdx.y * 128, b = blockIdx.z;
    __shared__ float As[32 * 128];   // [kk][m]
    __shared__ float Bs[32 * 128];   // [kk][n]
    const int tid = threadIdx.x;
    const int mg = tid >> 4, ng = tid & 15;

    u64t acc[4][8];
    #pragma unroll
    for (int i = 0; i < 4; i++)
        #pragma unroll
        for (int j = 0; j < 8; j++) acc[i][j] = 0ull;

    for (int kc = 0; kc < C_; kc += 32) {
        __syncthreads();
        #pragma unroll
        for (int i = 0; i < 4; i++) {
            int f = tid + i * 256;
            int kk = f >> 5, m4 = f & 31;
            *(float4*)&As[kk * 128 + m4 * 4] =
                *(const float4*)&x[(b * C_ + kc + kk) * T_ + t0 + m4 * 4];
            *(float4*)&Bs[kk * 128 + m4 * 4] =
                *(const float4*)&g_Wt[(kc + kk) * OCH + o0 + m4 * 4];
        }
        __syncthreads();
        #pragma unroll 4
        for (int kk = 0; kk < 32; kk++) {
            ulonglong2 a01 = *(const ulonglong2*)&As[kk * 128 + mg * 8];
            ulonglong2 a23 = *(const ulonglong2*)&As[kk * 128 + mg * 8 + 4];
            float4 bA = *(const float4*)&Bs[kk * 128 + ng * 8];
            float4 bB = *(const float4*)&Bs[kk * 128 + ng * 8 + 4];
            u64t av[4] = { a01.x, a01.y, a23.x, a23.y };
            u64t bd[8] = { dup2(bA.x), dup2(bA.y), dup2(bA.z), dup2(bA.w),
                           dup2(bB.x), dup2(bB.y), dup2(bB.z), dup2(bB.w) };
            #pragma unroll
            for (int i = 0; i < 4; i++)
                #pragma unroll
                for (int j = 0; j < 8; j++) fma2(acc[i][j], av[i], bd[j]);
        }
    }

    float bias[8];
    #pragma unroll
    for (int j = 0; j < 8; j++) bias[j] = g_bf[o0 + ng * 8 + j];

    #pragma unroll
    for (int i2 = 0; i2 < 4; i2++) {
        float lo[8], hi[8];
        #pragma unroll
        for (int j = 0; j < 8; j++) unpk(acc[i2][j], lo[j], hi[j]);
        int m = mg * 8 + 2 * i2;
        float4 v0, v1;
        v0.x = fmaxf(lo[0] + bias[0], 0.f); v0.y = fmaxf(lo[1] + bias[1], 0.f);
        v0.z = fmaxf(lo[2] + bias[2], 0.f); v0.w = fmaxf(lo[3] + bias[3], 0.f);
        v1.x = fmaxf(lo[4] + bias[4], 0.f); v1.y = fmaxf(lo[5] + bias[5], 0.f);
        v1.z = fmaxf(lo[6] + bias[6], 0.f); v1.w = fmaxf(lo[7] + bias[7], 0.f);
        *(float4*)&g_qkv[(b * T_ + t0 + m) * OCH + o0 + ng * 8]     = v0;
        *(float4*)&g_qkv[(b * T_ + t0 + m) * OCH + o0 + ng * 8 + 4] = v1;
        v0.x = fmaxf(hi[0] + bias[0], 0.f); v0.y = fmaxf(hi[1] + bias[1], 0.f);
        v0.z = fmaxf(hi[2] + bias[2], 0.f); v0.w = fmaxf(hi[3] + bias[3], 0.f);
        v1.x = fmaxf(hi[4] + bias[4], 0.f); v1.y = fmaxf(hi[5] + bias[5], 0.f);
        v1.z = fmaxf(hi[6] + bias[6], 0.f); v1.w = fmaxf(hi[7] + bias[7], 0.f);
        *(float4*)&g_qkv[(b * T_ + t0 + m + 1) * OCH + o0 + ng * 8]     = v0;
        *(float4*)&g_qkv[(b * T_ + t0 + m + 1) * OCH + o0 + ng * 8 + 4] = v1;
    }
}

// ---------------------------------------------------------------------------
// Banded attention, FFMA2 + warp-row mapping + 2 CTAs/SM.
// smem: Ss [64][324] | Qt [64 d][68] (aliased by Vs [16][256]) | Kt [64 d][34]
// Each warp owns 8 score rows -> P/Q smem loads are lane-uniform broadcasts.
// ---------------------------------------------------------------------------
template<bool DENOM>
__global__ __launch_bounds__(256, 2) void attn_k(const float* __restrict__ x,
                                                 float* __restrict__ y)
{
    extern __shared__ float sm[];
    float* Ss = sm;                          // 64*324
    float* Qt = sm + 64 * SSTR;              // 64*68   (transposed, pre-scaled)
    float* Kt = Qt + 64 * QSTR;              // 64*34
    float* Vs = Qt;                          // 16*256  (phase-2 alias)

    const int t0 = blockIdx.x * 64;
    const int b  = DENOM ? 0 : blockIdx.y;
    const int tid  = threadIdx.x;
    const int warp = tid >> 5, lane = tid & 31;
    const int r0 = warp * 8;
    const int sbase = t0 - DEPTH_;

    // ---- load Q transposed & pre-scaled by 1/sqrt(SC)=0.125 ----
    #pragma unroll
    for (int i = 0; i < 4; i++) {
        int f = tid + i * 256;
        int d4 = f & 15, r = (f >> 4) & 63;
        float4 v = *(const float4*)&g_qkv[(b * T_ + t0 + r) * OCH + d4 * 4];
        Qt[(d4 * 4 + 0) * QSTR + r] = v.x * 0.125f;
        Qt[(d4 * 4 + 1) * QSTR + r] = v.y * 0.125f;
        Qt[(d4 * 4 + 2) * QSTR + r] = v.z * 0.125f;
        Qt[(d4 * 4 + 3) * QSTR + r] = v.w * 0.125f;
    }

    // ---- scores: 10 chunks of 32 band columns ----
    for (int ch = 0; ch < 10; ch++) {
        int c0 = ch * 32;
        if (sbase + c0 + 31 < 0) continue;           // fully out of range (uniform)
        __syncthreads();
        #pragma unroll
        for (int i = 0; i < 2; i++) {
            int f = tid + i * 256;
            int d4 = f & 15, c = f >> 4;             // c in 0..31
            int s = sbase + c0 + c;
            float4 v = (s >= 0)
                ? *(const float4*)&g_qkv[(b * T_ + s) * OCH + 64 + d4 * 4]
                : make_float4(0.f, 0.f, 0.f, 0.f);
            Kt[(d4 * 4 + 0) * KSTR + c] = v.x;
            Kt[(d4 * 4 + 1) * KSTR + c] = v.y;
            Kt[(d4 * 4 + 2) * KSTR + c] = v.z;
            Kt[(d4 * 4 + 3) * KSTR + c] = v.w;
        }
        __syncthreads();
        u64t acc[4] = {0ull, 0ull, 0ull, 0ull};
        #pragma unroll 4
        for (int d = 0; d < 64; d++) {
            ulonglong2 qa = *(const ulonglong2*)&Qt[d * QSTR + r0];      // rows r0..r0+3
            ulonglong2 qb = *(const ulonglong2*)&Qt[d * QSTR + r0 + 4];  // rows r0+4..r0+7
            u64t k2 = dup2(Kt[d * KSTR + lane]);
            fma2(acc[0], qa.x, k2);
            fma2(acc[1], qa.y, k2);
            fma2(acc[2], qb.x, k2);
            fma2(acc[3], qb.y, k2);
        }
        int cc = c0 + lane;
        #pragma unroll
        for (int i2 = 0; i2 < 4; i2++) {
            float lo, hi; unpk(acc[i2], lo, hi);
            Ss[(r0 + 2 * i2) * SSTR + cc]     = lo;
            Ss[(r0 + 2 * i2 + 1) * SSTR + cc] = hi;
        }
    }
    __syncthreads();

    // ---- softmax (max includes 0 from masked entries, per reference) ----
    {
        int r = tid >> 2, g = tid & 3;
        int t = t0 + r;
        int jlo = max(r + 1, DEPTH_ - t0);
        int jhi = r + DEPTH_;
        float mx = 0.f;
        for (int j = jlo + g; j <= jhi; j += 4)
            mx = fmaxf(mx, Ss[r * SSTR + j]);
        mx = fmaxf(mx, __shfl_xor_sync(0xffffffffu, mx, 1));
        mx = fmaxf(mx, __shfl_xor_sync(0xffffffffu, mx, 2));
        if (DENOM) {
            float sum = 0.f;
            for (int j = jlo + g; j <= jhi; j += 4)
                sum += __expf(Ss[r * SSTR + j] - mx);
            sum += __shfl_xor_sync(0xffffffffu, sum, 1);
            sum += __shfl_xor_sync(0xffffffffu, sum, 2);
            if (g == 0) g_denom[t] = sum + 1e-30f;
        } else {
            float invd = 1.f / g_denom[t];
            for (int j = g; j < NCOL; j += 4) {
                float v = Ss[r * SSTR + j];
                Ss[r * SSTR + j] = (j >= jlo && j <= jhi) ? __expf(v - mx) * invd : 0.f;
            }
        }
    }
    if (DENOM) return;

    // ---- P @ V : warp rows r0..r0+7, lane cols lane*8..+7, 16-row V chunks ----
    const int cg8 = lane * 8;
    const int jloW = max(r0 + 1, DEPTH_ - t0);
    const int jhiW = r0 + 7 + DEPTH_;                // <= 319 always

    u64t acc[8][4];
    #pragma unroll
    for (int i = 0; i < 8; i++)
        #pragma unroll
        for (int j = 0; j < 4; j++) acc[i][j] = 0ull;

    for (int ch = 0; ch < 20; ch++) {
        int c0 = ch * 16;
        if (c0 + 15 < DEPTH_ - t0) continue;         // all p zero (uniform)
        __syncthreads();
        #pragma unroll
        for (int i = 0; i < 4; i++) {
            int f = tid + i * 256;
            int c4 = f & 63, row = f >> 6;           // row 0..15
            int s = sbase + c0 + row;
            float4 v = (s >= 0)
                ? *(const float4*)&g_qkv[(b * T_ + s) * OCH + 128 + c4 * 4]
                : make_float4(0.f, 0.f, 0.f, 0.f);
            *(float4*)&Vs[row * 256 + c4 * 4] = v;
        }
        __syncthreads();
        int jA = max(c0, jloW), jB = min(c0 + 15, jhiW);
        for (int jj = jA; jj <= jB; jj++) {
            int lrow = jj - c0;
            u64t pd[8];
            #pragma unroll
            for (int i = 0; i < 8; i++) pd[i] = dup2(Ss[(r0 + i) * SSTR + jj]);  // broadcast
            ulonglong2 v0 = *(const ulonglong2*)&Vs[lrow * 256 + cg8];
            ulonglong2 v1 = *(const ulonglong2*)&Vs[lrow * 256 + cg8 + 4];
            #pragma unroll
            for (int i = 0; i < 8; i++) {
                fma2(acc[i][0], pd[i], v0.x);
                fma2(acc[i][1], pd[i], v0.y);
                fma2(acc[i][2], pd[i], v1.x);
                fma2(acc[i][3], pd[i], v1.y);
            }
        }
    }

    // ---- epilogue: swizzled smem transpose, coalesced y = x + out ----
    __syncthreads();
    float* Outs = Ss;   // 256*64 floats needed, 64*324 available
    #pragma unroll
    for (int i = 0; i < 8; i++) {
        int r = r0 + i;
        #pragma unroll
        for (int j2 = 0; j2 < 4; j2++) {
            float lo, hi; unpk(acc[i][j2], lo, hi);
            int c = cg8 + 2 * j2;                      // even -> same swizzle for c,c+1
            int xr = r ^ ((c >> 2) & 63);
            Outs[c * 64 + xr]       = lo;
            Outs[(c + 1) * 64 + xr] = hi;
        }
    }
    __syncthreads();
    {
        int tt = tid & 63, grp = tid >> 6;
        #pragma unroll
        for (int k = 0; k < 64; k++) {
            int c = k * 4 + grp;
            int gi = (b * C_ + c) * T_ + t0 + tt;
            y[gi] = x[gi] + Outs[c * 64 + (tt ^ ((c >> 2) & 63))];
        }
    }
}

// ---------------------------------------------------------------------------
extern "C" void kernel_launch(void* const* d_in, const int* in_sizes, int n_in,
                              void* d_out, int out_size)
{
    const float* x   = (const float*)d_in[0];
    const float* kW  = (const float*)d_in[1];
    const float* kb  = (const float*)d_in[2];
    const float* kg  = (const float*)d_in[3];
    const float* kbe = (const float*)d_in[4];
    const float* kmu = (const float*)d_in[5];
    const float* kva = (const float*)d_in[6];
    const float* qW  = (const float*)d_in[7];
    const float* qb  = (const float*)d_in[8];
    const float* qg  = (const float*)d_in[9];
    const float* qbe = (const float*)d_in[10];
    const float* qmu = (const float*)d_in[11];
    const float* qva = (const float*)d_in[12];
    const float* vW  = (const float*)d_in[13];
    const float* vb  = (const float*)d_in[14];
    const float* vg  = (const float*)d_in[15];
    const float* vbe = (const float*)d_in[16];
    const float* vmu = (const float*)d_in[17];
    const float* vva = (const float*)d_in[18];
    float* y = (float*)d_out;

    const int smem_attn = (64 * SSTR + 64 * QSTR + 64 * KSTR) * sizeof(float); // 109056
    cudaFuncSetAttribute(attn_k<true>,  cudaFuncAttributeMaxDynamicSharedMemorySize, smem_attn);
    cudaFuncSetAttribute(attn_k<false>, cudaFuncAttributeMaxDynamicSharedMemorySize, smem_attn);

    fold_k<<<C_, OCH>>>(kW, kb, kg, kbe, kmu, kva,
                        qW, qb, qg, qbe, qmu, qva,
                        vW, vb, vg, vbe, vmu, vva);
    proj_k<<<dim3(T_ / 128, OCH / 128, B_), 256>>>(x);
    attn_k<true><<<T_ / 64, 256, smem_attn>>>(x, y);                 // batch-0 denominators
    attn_k<false><<<dim3(T_ / 64, B_), 256, smem_attn>>>(x, y);      // full attention
}

// round 5
// speedup vs baseline: 1.5866x; 1.0037x over previous
#include <cuda_runtime.h>
#include <math.h>

#define B_     8
#define C_     256
#define T_     2048
#define SC_    64
#define DEPTH_ 256
#define OCH    384          // q(64) | k(64) | v(256)
#define NCOL   320
#define SSTR   324          // score row stride (floats), 324 mod 32 = 4 -> low conflicts
#define QSTR   68           // Qt row stride: 68*4=272 bytes, 16B aligned
#define KSTR   34

typedef unsigned long long u64t;

// scratch (no allocation allowed)
__device__ float g_Wt[C_ * OCH];         // transposed folded weights [c][o]
__device__ float g_bf[OCH];
__device__ float g_qkv[B_ * T_ * OCH];   // [b][t][384] : q 0..63, k 64..127, v 128..383
__device__ float g_denom[T_];

// ---- packed fp32 helpers (FFMA2 via PTX; ptxas never emits it itself) ----
__device__ __forceinline__ u64t pk2(float a, float b) {
    u64t r; asm("mov.b64 %0,{%1,%2};" : "=l"(r) : "f"(a), "f"(b)); return r;
}
__device__ __forceinline__ u64t dup2(float a) { return pk2(a, a); }
__device__ __forceinline__ void fma2(u64t& d, u64t a, u64t b) {
    asm("fma.rn.f32x2 %0,%1,%2,%3;" : "=l"(d) : "l"(a), "l"(b), "l"(d));
}
__device__ __forceinline__ void unpk(u64t v, float& x, float& y) {
    asm("mov.b64 {%0,%1},%2;" : "=f"(x), "=f"(y) : "l"(v));
}

// ---------------------------------------------------------------------------
// Fold BN into conv weights, store TRANSPOSED: g_Wt[c][o] = W[o][c]*inv
// grid(C_) x block(OCH) -> coalesced g_Wt writes.
// ---------------------------------------------------------------------------
__global__ void fold_k(
    const float* __restrict__ kW, const float* __restrict__ kb, const float* __restrict__ kg,
    const float* __restrict__ kbe, const float* __restrict__ kmu, const float* __restrict__ kva,
    const float* __restrict__ qW, const float* __restrict__ qb, const float* __restrict__ qg,
    const float* __restrict__ qbe, const float* __restrict__ qmu, const float* __restrict__ qva,
    const float* __restrict__ vW, const float* __restrict__ vb, const float* __restrict__ vg,
    const float* __restrict__ vbe, const float* __restrict__ vmu, const float* __restrict__ vva)
{
    int c = blockIdx.x, o = threadIdx.x;
    const float *W, *bb, *gg, *be, *mu, *va; int oo;
    if (o < 64)        { W=qW; bb=qb; gg=qg; be=qbe; mu=qmu; va=qva; oo=o;       }
    else if (o < 128)  { W=kW; bb=kb; gg=kg; be=kbe; mu=kmu; va=kva; oo=o-64;   }
    else               { W=vW; bb=vb; gg=vg; be=vbe; mu=vmu; va=vva; oo=o-128;  }
    float inv = gg[oo] * rsqrtf(va[oo] + 1e-5f);
    g_Wt[c * OCH + o] = W[oo * C_ + c] * inv;
    if (c == 0) g_bf[o] = (bb[oo] - mu[oo]) * inv + be[oo];
}

// ---------------------------------------------------------------------------
// QKV projection: 128x128 tile, 256 threads, 8x8 per thread, FFMA2 packed
// over the m (row) dimension. grid (T/128, OCH/128, B).
// ---------------------------------------------------------------------------
__global__ __launch_bounds__(256, 2) void proj_k(const float* __restrict__ x)
{
    const int t0 = blockIdx.x * 128, o0 = blockIdx.y * 128, b = blockIdx.z;
    __shared__ float As[32 * 128];   // [kk][m]
    __shared__ float Bs[32 * 128];   // [kk][n]
    const int tid = threadIdx.x;
    const int mg = tid >> 4, ng = tid & 15;

    u64t acc[4][8];
    #pragma unroll
    for (int i = 0; i < 4; i++)
        #pragma unroll
        for (int j = 0; j < 8; j++) acc[i][j] = 0ull;

    for (int kc = 0; kc < C_; kc += 32) {
        __syncthreads();
        #pragma unroll
        for (int i = 0; i < 4; i++) {
            int f = tid + i * 256;
            int kk = f >> 5, m4 = f & 31;
            *(float4*)&As[kk * 128 + m4 * 4] =
                *(const float4*)&x[(b * C_ + kc + kk) * T_ + t0 + m4 * 4];
            *(float4*)&Bs[kk * 128 + m4 * 4] =
                *(const float4*)&g_Wt[(kc + kk) * OCH + o0 + m4 * 4];
        }
        __syncthreads();
        #pragma unroll 4
        for (int kk = 0; kk < 32; kk++) {
            ulonglong2 a01 = *(const ulonglong2*)&As[kk * 128 + mg * 8];
            ulonglong2 a23 = *(const ulonglong2*)&As[kk * 128 + mg * 8 + 4];
            float4 bA = *(const float4*)&Bs[kk * 128 + ng * 8];
            float4 bB = *(const float4*)&Bs[kk * 128 + ng * 8 + 4];
            u64t av[4] = { a01.x, a01.y, a23.x, a23.y };
            u64t bd[8] = { dup2(bA.x), dup2(bA.y), dup2(bA.z), dup2(bA.w),
                           dup2(bB.x), dup2(bB.y), dup2(bB.z), dup2(bB.w) };
            #pragma unroll
            for (int i = 0; i < 4; i++)
                #pragma unroll
                for (int j = 0; j < 8; j++) fma2(acc[i][j], av[i], bd[j]);
        }
    }

    float bias[8];
    #pragma unroll
    for (int j = 0; j < 8; j++) bias[j] = g_bf[o0 + ng * 8 + j];

    #pragma unroll
    for (int i2 = 0; i2 < 4; i2++) {
        float lo[8], hi[8];
        #pragma unroll
        for (int j = 0; j < 8; j++) unpk(acc[i2][j], lo[j], hi[j]);
        int m = mg * 8 + 2 * i2;
        float4 v0, v1;
        v0.x = fmaxf(lo[0] + bias[0], 0.f); v0.y = fmaxf(lo[1] + bias[1], 0.f);
        v0.z = fmaxf(lo[2] + bias[2], 0.f); v0.w = fmaxf(lo[3] + bias[3], 0.f);
        v1.x = fmaxf(lo[4] + bias[4], 0.f); v1.y = fmaxf(lo[5] + bias[5], 0.f);
        v1.z = fmaxf(lo[6] + bias[6], 0.f); v1.w = fmaxf(lo[7] + bias[7], 0.f);
        *(float4*)&g_qkv[(b * T_ + t0 + m) * OCH + o0 + ng * 8]     = v0;
        *(float4*)&g_qkv[(b * T_ + t0 + m) * OCH + o0 + ng * 8 + 4] = v1;
        v0.x = fmaxf(hi[0] + bias[0], 0.f); v0.y = fmaxf(hi[1] + bias[1], 0.f);
        v0.z = fmaxf(hi[2] + bias[2], 0.f); v0.w = fmaxf(hi[3] + bias[3], 0.f);
        v1.x = fmaxf(hi[4] + bias[4], 0.f); v1.y = fmaxf(hi[5] + bias[5], 0.f);
        v1.z = fmaxf(hi[6] + bias[6], 0.f); v1.w = fmaxf(hi[7] + bias[7], 0.f);
        *(float4*)&g_qkv[(b * T_ + t0 + m + 1) * OCH + o0 + ng * 8]     = v0;
        *(float4*)&g_qkv[(b * T_ + t0 + m + 1) * OCH + o0 + ng * 8 + 4] = v1;
    }
}

// ---------------------------------------------------------------------------
// Banded attention, FFMA2 + warp-row mapping + 2 CTAs/SM.
// smem: Ss [64][324] | Qt [64 d][68] (aliased by Vs [16][256]) | Kt [64 d][34]
// Each warp owns 8 score rows -> P/Q smem loads are lane-uniform broadcasts.
// ---------------------------------------------------------------------------
template<bool DENOM>
__global__ __launch_bounds__(256, 2) void attn_k(const float* __restrict__ x,
                                                 float* __restrict__ y)
{
    extern __shared__ float sm[];
    float* Ss = sm;                          // 64*324
    float* Qt = sm + 64 * SSTR;              // 64*68   (transposed, pre-scaled)
    float* Kt = Qt + 64 * QSTR;              // 64*34
    float* Vs = Qt;                          // 16*256  (phase-2 alias)

    const int t0 = blockIdx.x * 64;
    const int b  = DENOM ? 0 : blockIdx.y;
    const int tid  = threadIdx.x;
    const int warp = tid >> 5, lane = tid & 31;
    const int r0 = warp * 8;
    const int sbase = t0 - DEPTH_;

    // ---- load Q transposed & pre-scaled by 1/sqrt(SC)=0.125 ----
    #pragma unroll
    for (int i = 0; i < 4; i++) {
        int f = tid + i * 256;
        int d4 = f & 15, r = (f >> 4) & 63;
        float4 v = *(const float4*)&g_qkv[(b * T_ + t0 + r) * OCH + d4 * 4];
        Qt[(d4 * 4 + 0) * QSTR + r] = v.x * 0.125f;
        Qt[(d4 * 4 + 1) * QSTR + r] = v.y * 0.125f;
        Qt[(d4 * 4 + 2) * QSTR + r] = v.z * 0.125f;
        Qt[(d4 * 4 + 3) * QSTR + r] = v.w * 0.125f;
    }

    // ---- scores: 10 chunks of 32 band columns ----
    for (int ch = 0; ch < 10; ch++) {
        int c0 = ch * 32;
        if (sbase + c0 + 31 < 0) continue;           // fully out of range (uniform)
        __syncthreads();
        #pragma unroll
        for (int i = 0; i < 2; i++) {
            int f = tid + i * 256;
            int d4 = f & 15, c = f >> 4;             // c in 0..31
            int s = sbase + c0 + c;
            float4 v = (s >= 0)
                ? *(const float4*)&g_qkv[(b * T_ + s) * OCH + 64 + d4 * 4]
                : make_float4(0.f, 0.f, 0.f, 0.f);
            Kt[(d4 * 4 + 0) * KSTR + c] = v.x;
            Kt[(d4 * 4 + 1) * KSTR + c] = v.y;
            Kt[(d4 * 4 + 2) * KSTR + c] = v.z;
            Kt[(d4 * 4 + 3) * KSTR + c] = v.w;
        }
        __syncthreads();
        u64t acc[4] = {0ull, 0ull, 0ull, 0ull};
        #pragma unroll 4
        for (int d = 0; d < 64; d++) {
            ulonglong2 qa = *(const ulonglong2*)&Qt[d * QSTR + r0];      // rows r0..r0+3
            ulonglong2 qb = *(const ulonglong2*)&Qt[d * QSTR + r0 + 4];  // rows r0+4..r0+7
            u64t k2 = dup2(Kt[d * KSTR + lane]);
            fma2(acc[0], qa.x, k2);
            fma2(acc[1], qa.y, k2);
            fma2(acc[2], qb.x, k2);
            fma2(acc[3], qb.y, k2);
        }
        int cc = c0 + lane;
        #pragma unroll
        for (int i2 = 0; i2 < 4; i2++) {
            float lo, hi; unpk(acc[i2], lo, hi);
            Ss[(r0 + 2 * i2) * SSTR + cc]     = lo;
            Ss[(r0 + 2 * i2 + 1) * SSTR + cc] = hi;
        }
    }
    __syncthreads();

    // ---- softmax (max includes 0 from masked entries, per reference) ----
    {
        int r = tid >> 2, g = tid & 3;
        int t = t0 + r;
        int jlo = max(r + 1, DEPTH_ - t0);
        int jhi = r + DEPTH_;
        float mx = 0.f;
        for (int j = jlo + g; j <= jhi; j += 4)
            mx = fmaxf(mx, Ss[r * SSTR + j]);
        mx = fmaxf(mx, __shfl_xor_sync(0xffffffffu, mx, 1));
        mx = fmaxf(mx, __shfl_xor_sync(0xffffffffu, mx, 2));
        if (DENOM) {
            float sum = 0.f;
            for (int j = jlo + g; j <= jhi; j += 4)
                sum += __expf(Ss[r * SSTR + j] - mx);
            sum += __shfl_xor_sync(0xffffffffu, sum, 1);
            sum += __shfl_xor_sync(0xffffffffu, sum, 2);
            if (g == 0) g_denom[t] = sum + 1e-30f;
        } else {
            float invd = 1.f / g_denom[t];
            for (int j = g; j < NCOL; j += 4) {
                float v = Ss[r * SSTR + j];
                Ss[r * SSTR + j] = (j >= jlo && j <= jhi) ? __expf(v - mx) * invd : 0.f;
            }
        }
    }
    if (DENOM) return;

    // ---- P @ V : warp rows r0..r0+7, lane cols lane*8..+7, 16-row V chunks ----
    const int cg8 = lane * 8;
    const int jloW = max(r0 + 1, DEPTH_ - t0);
    const int jhiW = r0 + 7 + DEPTH_;                // <= 319 always

    u64t acc[8][4];
    #pragma unroll
    for (int i = 0; i < 8; i++)
        #pragma unroll
        for (int j = 0; j < 4; j++) acc[i][j] = 0ull;

    for (int ch = 0; ch < 20; ch++) {
        int c0 = ch * 16;
        if (c0 + 15 < DEPTH_ - t0) continue;         // all p zero (uniform)
        __syncthreads();
        #pragma unroll
        for (int i = 0; i < 4; i++) {
            int f = tid + i * 256;
            int c4 = f & 63, row = f >> 6;           // row 0..15
            int s = sbase + c0 + row;
            float4 v = (s >= 0)
                ? *(const float4*)&g_qkv[(b * T_ + s) * OCH + 128 + c4 * 4]
                : make_float4(0.f, 0.f, 0.f, 0.f);
            *(float4*)&Vs[row * 256 + c4 * 4] = v;
        }
        __syncthreads();
        int jA = max(c0, jloW), jB = min(c0 + 15, jhiW);
        for (int jj = jA; jj <= jB; jj++) {
            int lrow = jj - c0;
            u64t pd[8];
            #pragma unroll
            for (int i = 0; i < 8; i++) pd[i] = dup2(Ss[(r0 + i) * SSTR + jj]);  // broadcast
            ulonglong2 v0 = *(const ulonglong2*)&Vs[lrow * 256 + cg8];
            ulonglong2 v1 = *(const ulonglong2*)&Vs[lrow * 256 + cg8 + 4];
            #pragma unroll
            for (int i = 0; i < 8; i++) {
                fma2(acc[i][0], pd[i], v0.x);
                fma2(acc[i][1], pd[i], v0.y);
                fma2(acc[i][2], pd[i], v1.x);
                fma2(acc[i][3], pd[i], v1.y);
            }
        }
    }

    // ---- epilogue: swizzled smem transpose, coalesced y = x + out ----
    __syncthreads();
    float* Outs = Ss;   // 256*64 floats needed, 64*324 available
    #pragma unroll
    for (int i = 0; i < 8; i++) {
        int r = r0 + i;
        #pragma unroll
        for (int j2 = 0; j2 < 4; j2++) {
            float lo, hi; unpk(acc[i][j2], lo, hi);
            int c = cg8 + 2 * j2;                      // even -> same swizzle for c,c+1
            int xr = r ^ ((c >> 2) & 63);
            Outs[c * 64 + xr]       = lo;
            Outs[(c + 1) * 64 + xr] = hi;
        }
    }
    __syncthreads();
    {
        int tt = tid & 63, grp = tid >> 6;
        #pragma unroll
        for (int k = 0; k < 64; k++) {
            int c = k * 4 + grp;
            int gi = (b * C_ + c) * T_ + t0 + tt;
            y[gi] = x[gi] + Outs[c * 64 + (tt ^ ((c >> 2) & 63))];
        }
    }
}

// ---------------------------------------------------------------------------
extern "C" void kernel_launch(void* const* d_in, const int* in_sizes, int n_in,
                              void* d_out, int out_size)
{
    const float* x   = (const float*)d_in[0];
    const float* kW  = (const float*)d_in[1];
    const float* kb  = (const float*)d_in[2];
    const float* kg  = (const float*)d_in[3];
    const float* kbe = (const float*)d_in[4];
    const float* kmu = (const float*)d_in[5];
    const float* kva = (const float*)d_in[6];
    const float* qW  = (const float*)d_in[7];
    const float* qb  = (const float*)d_in[8];
    const float* qg  = (const float*)d_in[9];
    const float* qbe = (const float*)d_in[10];
    const float* qmu = (const float*)d_in[11];
    const float* qva = (const float*)d_in[12];
    const float* vW  = (const float*)d_in[13];
    const float* vb  = (const float*)d_in[14];
    const float* vg  = (const float*)d_in[15];
    const float* vbe = (const float*)d_in[16];
    const float* vmu = (const float*)d_in[17];
    const float* vva = (const float*)d_in[18];
    float* y = (float*)d_out;

    const int smem_attn = (64 * SSTR + 64 * QSTR + 64 * KSTR) * sizeof(float); // 109056
    cudaFuncSetAttribute(attn_k<true>,  cudaFuncAttributeMaxDynamicSharedMemorySize, smem_attn);
    cudaFuncSetAttribute(attn_k<false>, cudaFuncAttributeMaxDynamicSharedMemorySize, smem_attn);

    fold_k<<<C_, OCH>>>(kW, kb, kg, kbe, kmu, kva,
                        qW, qb, qg, qbe, qmu, qva,
                        vW, vb, vg, vbe, vmu, vva);
    proj_k<<<dim3(T_ / 128, OCH / 128, B_), 256>>>(x);
    attn_k<true><<<T_ / 64, 256, smem_attn>>>(x, y);                 // batch-0 denominators
    attn_k<false><<<dim3(T_ / 64, B_), 256, smem_attn>>>(x, y);      // full attention
}